// round 9
// baseline (speedup 1.0000x reference)
#include <cuda_runtime.h>
#include <cuda_fp16.h>

#define BB   256
#define TT   2048
#define QD   1024
#define AD   128
#define DCH  8
#define DKK  21
#define PLL  11
#define MH_STRIDE 24   // half2 per M row: taps 0..20, [21]=(tb,tb), [22..23]=0
#define SALN 2080      // fp32 padded alignment (10 left pad + tail zeros)
#define NPAIR 1038
#define NTHR 256       // 8 positions per thread

__device__ __forceinline__ float warp_sum(float v) {
#pragma unroll
    for (int o = 16; o; o >>= 1) v += __shfl_xor_sync(~0u, v, o);
    return v;
}

__device__ __forceinline__ __half2 tanh2(__half2 x) {
    unsigned xi = *reinterpret_cast<unsigned*>(&x), yi;
    asm("tanh.approx.f16x2 %0, %1;" : "=r"(yi) : "r"(xi));
    return *reinterpret_cast<__half2*>(&yi);
}

// ---------------------------------------------------------------------------
// Fully fused, fp16x2 conv core, 8 positions/thread for ILP.
// One block per batch.
// ---------------------------------------------------------------------------
__global__ __launch_bounds__(NTHR, 3) void dca_fused_kernel(
    const float* __restrict__ query,     const float* __restrict__ alignment,
    const float* __restrict__ P,         const float* __restrict__ W_w,
    const float* __restrict__ W_b,       const float* __restrict__ V_w,
    const float* __restrict__ F_w,       const float* __restrict__ U_w,
    const float* __restrict__ T_w,       const float* __restrict__ T_b,
    const float* __restrict__ v_w,       float* __restrict__ out)
{
    __shared__ float   sal[SALN];              // fp32 padded alignment (prior)
    __shared__ __half2 pe[NPAIR];              // (sal[2j],   sal[2j+1])
    __shared__ __half2 po[NPAIR];              // (sal[2j+1], sal[2j+2])
    __shared__ __half2 mh[AD * MH_STRIDE];     // duplicated fp16 M rows
    __shared__ float   sv[AD];                 // v weights fp32
    __shared__ float   shq[QD];
    __shared__ float   shh[AD];
    __shared__ float   shG[DCH * DKK];
    __shared__ float   sp[PLL];
    __shared__ float   red[8];

    const int b = blockIdx.x, tid = threadIdx.x;
    const int lane = tid & 31, wrp = tid >> 5;   // 8 warps

    // ---- loads ----
    for (int i = tid; i < QD; i += NTHR) shq[i] = query[b * QD + i];
    for (int i = tid; i < TT; i += NTHR) sal[10 + i] = alignment[b * TT + i];
    if (tid < 10) sal[tid] = 0.f;
    for (int i = TT + 10 + tid; i < SALN; i += NTHR) sal[i] = 0.f;
    if (tid < PLL) sp[tid] = P[tid];
    __syncthreads();

    // ---- half2 window pair tables ----
    for (int j = tid; j < NPAIR; j += NTHR) {
        pe[j] = __floats2half2_rn(sal[2 * j],     sal[2 * j + 1]);
        po[j] = __floats2half2_rn(sal[2 * j + 1], sal[2 * j + 2]);
    }

    // ---- phase A1: h[a] = tanh(dot(q, W_w[a,:]) + W_b[a]) ----
    // 8 warps x 16 rows each, row pairs for load-level parallelism.
#pragma unroll 1
    for (int i = 0; i < 16; i += 2) {
        const int a0 = wrp * 16 + i, a1 = a0 + 1;
        const float4* wr0 = (const float4*)(W_w + a0 * QD);
        const float4* wr1 = (const float4*)(W_w + a1 * QD);
        float d0 = 0.f, d1 = 0.f;
#pragma unroll
        for (int j = 0; j < 8; j++) {
            const float4 qv = *(const float4*)&shq[4 * lane + 128 * j];
            const float4 w0 = wr0[lane + 32 * j];
            const float4 w1 = wr1[lane + 32 * j];
            d0 += w0.x * qv.x + w0.y * qv.y + w0.z * qv.z + w0.w * qv.w;
            d1 += w1.x * qv.x + w1.y * qv.y + w1.z * qv.z + w1.w * qv.w;
        }
        d0 = warp_sum(d0);
        d1 = warp_sum(d1);
        if (lane == 0) {
            shh[a0] = tanhf(d0 + W_b[a0]);
            shh[a1] = tanhf(d1 + W_b[a1]);
        }
    }
    __syncthreads();

    // ---- phase A2: G[r] = dot(h, V_w[r,:]) ----
    for (int r = tid; r < DCH * DKK; r += NTHR) {
        const float4* vr = (const float4*)(V_w + r * AD);
        const float4* hr = (const float4*)shh;
        float acc = 0.f;
#pragma unroll
        for (int j = 0; j < AD / 4; j++) {
            const float4 vv = vr[j], hv = hr[j];
            acc += vv.x * hv.x + vv.y * hv.y + vv.z * hv.z + vv.w * hv.w;
        }
        shG[r] = acc;
    }
    __syncthreads();

    // ---- phase A3: M[a,k] -> duplicated half2; tb folded; v fp32 ----
    for (int i = tid; i < AD * DKK; i += NTHR) {
        const int a = i / DKK, k = i - a * DKK;
        float m = 0.f;
#pragma unroll
        for (int c = 0; c < DCH; c++)
            m += U_w[a * DCH + c] * F_w[c * DKK + k]
               + T_w[a * DCH + c] * shG[c * DKK + k];
        const __half hm = __float2half_rn(m);
        mh[a * MH_STRIDE + k] = __halves2half2(hm, hm);
    }
    if (tid < AD) {
        const __half htb = __float2half_rn(T_b[tid]);
        mh[tid * MH_STRIDE + 21] = __halves2half2(htb, htb);
        mh[tid * MH_STRIDE + 22] = __halves2half2(__half(0.f), __half(0.f));
        mh[tid * MH_STRIDE + 23] = __halves2half2(__half(0.f), __half(0.f));
        sv[tid] = v_w[tid];
    }
    __syncthreads();

    // ---- phase B: conv via HFMA2, 8 positions per thread, 4 acc chains ----
    const int t0 = tid * 8;   // padded start index

    // u[k] = (sal[t0+k], sal[t0+k+1]) as half2, k = 0..26
    __half2 u[27];
#pragma unroll
    for (int k = 0; k < 27; k++)
        u[k] = (k & 1) ? po[(t0 + k - 1) >> 1] : pe[(t0 + k) >> 1];

    float e0 = 0.f, e1 = 0.f, e2 = 0.f, e3 = 0.f;
    float e4 = 0.f, e5 = 0.f, e6 = 0.f, e7 = 0.f;

#pragma unroll 1
    for (int a = 0; a < AD; a++) {
        const __half2* row = mh + a * MH_STRIDE;
        const uint4 q5 = *(const uint4*)(row + 20);   // tap20, (tb,tb), 0, 0
        const __half2 tap20 = ((const __half2*)&q5)[0];
        const __half2 tbtb  = ((const __half2*)&q5)[1];
        __half2 acc0 = tbtb, acc1 = tbtb, acc2 = tbtb, acc3 = tbtb;
#pragma unroll
        for (int c = 0; c < 5; c++) {
            const uint4 qc = *(const uint4*)(row + 4 * c);
            const __half2* t4 = (const __half2*)&qc;
#pragma unroll
            for (int i = 0; i < 4; i++) {
                const int k = 4 * c + i;
                acc0 = __hfma2(t4[i], u[k],     acc0);
                acc1 = __hfma2(t4[i], u[k + 2], acc1);
                acc2 = __hfma2(t4[i], u[k + 4], acc2);
                acc3 = __hfma2(t4[i], u[k + 6], acc3);
            }
        }
        acc0 = __hfma2(tap20, u[20], acc0);
        acc1 = __hfma2(tap20, u[22], acc1);
        acc2 = __hfma2(tap20, u[24], acc2);
        acc3 = __hfma2(tap20, u[26], acc3);

        const float2 f0 = __half22float2(tanh2(acc0));
        const float2 f1 = __half22float2(tanh2(acc1));
        const float2 f2 = __half22float2(tanh2(acc2));
        const float2 f3 = __half22float2(tanh2(acc3));
        const float v = sv[a];
        e0 += v * f0.x; e1 += v * f0.y;
        e2 += v * f1.x; e3 += v * f1.y;
        e4 += v * f2.x; e5 += v * f2.y;
        e6 += v * f3.x; e7 += v * f3.y;
    }

    // ---- prior in exact fp32 ----
    {
        float s0 = 0.f, s1 = 0.f, s2 = 0.f, s3 = 0.f;
        float s4 = 0.f, s5 = 0.f, s6 = 0.f, s7 = 0.f;
#pragma unroll
        for (int k = 0; k < PLL; k++) {
            const float pk = sp[k];
            s0 += pk * sal[t0 + k];     s1 += pk * sal[t0 + k + 1];
            s2 += pk * sal[t0 + k + 2]; s3 += pk * sal[t0 + k + 3];
            s4 += pk * sal[t0 + k + 4]; s5 += pk * sal[t0 + k + 5];
            s6 += pk * sal[t0 + k + 6]; s7 += pk * sal[t0 + k + 7];
        }
        e0 += __logf(fmaxf(s0, 1e-6f));
        e1 += __logf(fmaxf(s1, 1e-6f));
        e2 += __logf(fmaxf(s2, 1e-6f));
        e3 += __logf(fmaxf(s3, 1e-6f));
        e4 += __logf(fmaxf(s4, 1e-6f));
        e5 += __logf(fmaxf(s5, 1e-6f));
        e6 += __logf(fmaxf(s6, 1e-6f));
        e7 += __logf(fmaxf(s7, 1e-6f));
    }

    // ---- softmax over T within the block ----
    float mx = fmaxf(fmaxf(fmaxf(e0, e1), fmaxf(e2, e3)),
                     fmaxf(fmaxf(e4, e5), fmaxf(e6, e7)));
#pragma unroll
    for (int o = 16; o; o >>= 1) mx = fmaxf(mx, __shfl_xor_sync(~0u, mx, o));
    if (lane == 0) red[wrp] = mx;
    __syncthreads();
    mx = red[0];
#pragma unroll
    for (int i = 1; i < 8; i++) mx = fmaxf(mx, red[i]);
    __syncthreads();

    const float x0 = __expf(e0 - mx), x1 = __expf(e1 - mx);
    const float x2 = __expf(e2 - mx), x3 = __expf(e3 - mx);
    const float x4 = __expf(e4 - mx), x5 = __expf(e5 - mx);
    const float x6 = __expf(e6 - mx), x7 = __expf(e7 - mx);
    float sm = ((x0 + x1) + (x2 + x3)) + ((x4 + x5) + (x6 + x7));
#pragma unroll
    for (int o = 16; o; o >>= 1) sm += __shfl_xor_sync(~0u, sm, o);
    if (lane == 0) red[wrp] = sm;
    __syncthreads();
    sm = red[0];
#pragma unroll
    for (int i = 1; i < 8; i++) sm += red[i];

    const float inv = 1.0f / sm;
    float4* o4 = (float4*)(out + b * TT + t0);
    o4[0] = make_float4(x0 * inv, x1 * inv, x2 * inv, x3 * inv);
    o4[1] = make_float4(x4 * inv, x5 * inv, x6 * inv, x7 * inv);
}

extern "C" void kernel_launch(void* const* d_in, const int* in_sizes, int n_in,
                              void* d_out, int out_size)
{
    const float* query     = (const float*)d_in[0];
    const float* alignment = (const float*)d_in[1];
    const float* P         = (const float*)d_in[2];
    const float* W_w       = (const float*)d_in[3];
    const float* W_b       = (const float*)d_in[4];
    const float* V_w       = (const float*)d_in[5];
    const float* F_w       = (const float*)d_in[6];
    const float* U_w       = (const float*)d_in[7];
    const float* T_w       = (const float*)d_in[8];
    const float* T_b       = (const float*)d_in[9];
    const float* v_w       = (const float*)d_in[10];
    float* out = (float*)d_out;

    dca_fused_kernel<<<BB, NTHR>>>(query, alignment, P, W_w, W_b, V_w,
                                   F_w, U_w, T_w, T_b, v_w, out);
}